// round 1
// baseline (speedup 1.0000x reference)
#include <cuda_runtime.h>
#include <cstdint>

// ---------------- problem constants ----------------
#define BATCH    4096
#define N_COL    100
#define N_COND   64
#define DD       4
#define TOTAL    6400      // N_COL*N_COND
#define N_RODT   1600      // TOTAL/DD
#define N_EST    160
#define N_FOREST 100
#define N_HID    128
#define N_CLASS  10
#define EPSV     1e-5f

// ---------------- device scratch (no allocation allowed) ----------------
__device__ float g_xT[N_COL * BATCH];                      // 1.6 MB  x transposed [c][b]
__device__ float g_wT[N_RODT * BATCH];                     // 26 MB   rODT weights transposed [g][b]
__device__ float g_F [(size_t)N_FOREST * BATCH * N_HID];   // 210 MB  forest embeddings, rows r=f*4096+b
__device__ float g_Y [(size_t)N_FOREST * BATCH * N_CLASS]; // 16 MB   per-forest logits

// =====================================================================
// Kernel 0: transpose x [B,100] -> xT [100,B]
// =====================================================================
__global__ void k0_transpose(const float* __restrict__ x) {
    int i = blockIdx.x * 256 + threadIdx.x;   // i = c*4096 + b
    int c = i >> 12;          // /4096
    int b = i & 4095;
    g_xT[i] = x[b * N_COL + c];
}

// =====================================================================
// Kernel 1: steps 1-6 fused.  block = one rODT group g x 256 b's.
// per (b,g): 4 sigmoids -> GN(4) -> 4x4 conv -> relu -> GN(4) -> 4x1 conv
// =====================================================================
__global__ void k1_rodt(const float* __restrict__ w1, const float* __restrict__ b1,
                        const int*   __restrict__ perm,
                        const float* __restrict__ gn1w, const float* __restrict__ gn1b,
                        const float* __restrict__ c2w,  const float* __restrict__ c2b,
                        const float* __restrict__ gn2w, const float* __restrict__ gn2b,
                        const float* __restrict__ c3w,  const float* __restrict__ c3b) {
    int g   = blockIdx.x;
    int tid = threadIdx.x;
    __shared__ int   sc[4];
    __shared__ float sw1[4], sb1[4], sg1w[4], sg1b[4];
    __shared__ float sw2[16], sb2[4], sg2w[4], sg2b[4], sw3[4], sb3;
    if (tid < 4) {
        int t = 4 * g + tid;
        int p = perm[t];
        int c = p % N_COL;
        int j = p / N_COL;
        sc [tid] = c;
        sw1[tid] = w1[c * N_COND + j];
        sb1[tid] = b1[c * N_COND + j];
        sg1w[tid] = gn1w[t];  sg1b[tid] = gn1b[t];
        sb2 [tid] = c2b[t];
        sg2w[tid] = gn2w[t];  sg2b[tid] = gn2b[t];
        sw3 [tid] = c3w[g * 4 + tid];
    }
    if (tid < 16) sw2[tid] = c2w[g * 16 + tid];
    if (tid == 31) sb3 = c3b[g];
    __syncthreads();

    int b = blockIdx.y * 256 + tid;
    float v[4];
#pragma unroll
    for (int k = 0; k < 4; k++) {
        float z = fmaf(g_xT[sc[k] * BATCH + b], sw1[k], sb1[k]);
        v[k] = 1.f / (1.f + __expf(-z));
    }
    // GN1
    float mu = 0.25f * (v[0] + v[1] + v[2] + v[3]);
    float var = 0.f;
#pragma unroll
    for (int k = 0; k < 4; k++) { float d = v[k] - mu; var += d * d; }
    var *= 0.25f;
    float rs = rsqrtf(var + EPSV);
    float n[4];
#pragma unroll
    for (int k = 0; k < 4; k++) n[k] = fmaf((v[k] - mu) * rs, sg1w[k], sg1b[k]);
    // 4x4 grouped conv + relu
    float h[4];
#pragma unroll
    for (int o = 0; o < 4; o++) {
        float a = sb2[o];
#pragma unroll
        for (int k = 0; k < 4; k++) a = fmaf(n[k], sw2[k * 4 + o], a);
        h[o] = fmaxf(a, 0.f);
    }
    // GN2
    float mu2 = 0.25f * (h[0] + h[1] + h[2] + h[3]);
    float var2 = 0.f;
#pragma unroll
    for (int k = 0; k < 4; k++) { float d = h[k] - mu2; var2 += d * d; }
    var2 *= 0.25f;
    float rs2 = rsqrtf(var2 + EPSV);
    float wo = sb3;
#pragma unroll
    for (int k = 0; k < 4; k++)
        wo = fmaf(fmaf((h[k] - mu2) * rs2, sg2w[k], sg2b[k]), sw3[k], wo);
    g_wT[(size_t)g * BATCH + b] = wo;
}

// =====================================================================
// Kernel 2: per forest: gather + softmax + [128b x 160e] @ [160e x 128d]
// block: (b-tile 128, forest f). 256 threads, 8x8 micro-tile fp32 GEMM.
// smem: ws[160][132] (softmax probs, e-major), Es[16][132], idx[160]
// =====================================================================
#define K2_SMEM ((160 * 132 + 16 * 132 + 160) * 4)
__global__ void __launch_bounds__(256) k2_forest(const int* __restrict__ swr,
                                                 const float* __restrict__ E) {
    extern __shared__ float sh[];
    float* ws  = sh;                    // 160*132
    float* Es  = sh + 160 * 132;        // 16*132
    int*   idx = (int*)(Es + 16 * 132); // 160
    int f   = blockIdx.y;
    int b0  = blockIdx.x * 128;
    int tid = threadIdx.x;

    if (tid < N_EST) idx[tid] = swr[f * N_EST + tid];
    __syncthreads();

    // load w tile transposed: ws[e][b]
#pragma unroll 4
    for (int i = tid; i < 160 * 128; i += 256) {
        int e  = i >> 7;
        int bb = i & 127;
        ws[e * 132 + bb] = g_wT[(size_t)idx[e] * BATCH + b0 + bb];
    }
    __syncthreads();

    // row-wise softmax over e (threads 0..127, one row each; conflict-free banks)
    if (tid < 128) {
        float m = -1e30f;
        for (int e = 0; e < 160; e++) m = fmaxf(m, ws[e * 132 + tid]);
        float s = 0.f;
        for (int e = 0; e < 160; e++) {
            float p = __expf(ws[e * 132 + tid] - m);
            ws[e * 132 + tid] = p;
            s += p;
        }
        float inv = 1.f / s;
        for (int e = 0; e < 160; e++) ws[e * 132 + tid] *= inv;
    }
    __syncthreads();

    // GEMM: C[b][d] = sum_e ws[e][b] * E[idx[e]][d]
    int tx = tid & 15;   // d / 8
    int ty = tid >> 4;   // b / 8
    float acc[8][8];
#pragma unroll
    for (int i = 0; i < 8; i++)
#pragma unroll
        for (int j = 0; j < 8; j++) acc[i][j] = 0.f;

    for (int k0 = 0; k0 < 160; k0 += 16) {
#pragma unroll 2
        for (int i = tid; i < 16 * 128; i += 256) {
            int kk = i >> 7;
            int d  = i & 127;
            Es[kk * 132 + d] = E[(size_t)idx[k0 + kk] * N_HID + d];
        }
        __syncthreads();
#pragma unroll
        for (int kk = 0; kk < 16; kk++) {
            float4 a0 = *(const float4*)&ws[(k0 + kk) * 132 + ty * 8];
            float4 a1 = *(const float4*)&ws[(k0 + kk) * 132 + ty * 8 + 4];
            float4 bv0 = *(const float4*)&Es[kk * 132 + tx * 8];
            float4 bv1 = *(const float4*)&Es[kk * 132 + tx * 8 + 4];
            float a[8] = {a0.x, a0.y, a0.z, a0.w, a1.x, a1.y, a1.z, a1.w};
            float bb[8] = {bv0.x, bv0.y, bv0.z, bv0.w, bv1.x, bv1.y, bv1.z, bv1.w};
#pragma unroll
            for (int i = 0; i < 8; i++)
#pragma unroll
                for (int j = 0; j < 8; j++) acc[i][j] = fmaf(a[i], bb[j], acc[i][j]);
        }
        __syncthreads();
    }

    // write F tile: row r = f*4096 + b0 + (ty*8+i), col tx*8+j
#pragma unroll
    for (int i = 0; i < 8; i++) {
        size_t r = (size_t)f * BATCH + b0 + ty * 8 + i;
        float4 o0 = make_float4(acc[i][0], acc[i][1], acc[i][2], acc[i][3]);
        float4 o1 = make_float4(acc[i][4], acc[i][5], acc[i][6], acc[i][7]);
        *(float4*)&g_F[r * N_HID + tx * 8]     = o0;
        *(float4*)&g_F[r * N_HID + tx * 8 + 4] = o1;
    }
}

// =====================================================================
// Kernel 3: fused MLP per row (b,f): LN1 -> fc1(128x128)+relu -> LN2 -> fc2(128x10)
// block = 128 rows, 256 threads. dynamic smem: XT[128][132] + W1[128][132]
// =====================================================================
#define K3_SMEM ((128 * 132 * 2) * 4)
__global__ void __launch_bounds__(256) k3_mlp(const float* __restrict__ ln1w, const float* __restrict__ ln1b,
                                              const float* __restrict__ fc1w, const float* __restrict__ fc1b,
                                              const float* __restrict__ ln2w, const float* __restrict__ ln2b,
                                              const float* __restrict__ fc2w, const float* __restrict__ fc2b) {
    extern __shared__ float sh[];
    float* XT = sh;               // [k][132] normalized-input transposed; later reused as H[row][132]
    float* W1 = sh + 128 * 132;   // fc1 weights [k][132]
    __shared__ float s_ln1w[128], s_ln1b[128], s_fc1b[128], s_ln2w[128], s_ln2b[128];
    __shared__ float s_fc2w[128 * 10], s_fc2b[16];

    int tid = threadIdx.x;
    size_t row0 = (size_t)blockIdx.x * 128;

    if (tid < 128) {
        s_ln1w[tid] = ln1w[tid]; s_ln1b[tid] = ln1b[tid];
        s_fc1b[tid] = fc1b[tid];
        s_ln2w[tid] = ln2w[tid]; s_ln2b[tid] = ln2b[tid];
    }
    for (int i = tid; i < 1280; i += 256) s_fc2w[i] = fc2w[i];
    if (tid < 10) s_fc2b[tid] = fc2b[tid];
    // load fc1 weights
#pragma unroll 4
    for (int i = tid; i < 128 * 128; i += 256) {
        int k = i >> 7, o = i & 127;
        W1[k * 132 + o] = fc1w[i];
    }
    __syncthreads();

    // LN1 + transpose: warp per row (16 rows/warp)
    int warp = tid >> 5, lane = tid & 31;
    for (int it = 0; it < 16; it++) {
        int r = warp + it * 8;          // local row
        float4 xv = *(const float4*)&g_F[(row0 + r) * N_HID + lane * 4];
        float s = xv.x + xv.y + xv.z + xv.w;
#pragma unroll
        for (int o = 16; o > 0; o >>= 1) s += __shfl_xor_sync(0xffffffff, s, o);
        float mu = s * (1.f / 128.f);
        float d0 = xv.x - mu, d1 = xv.y - mu, d2 = xv.z - mu, d3 = xv.w - mu;
        float q = d0 * d0 + d1 * d1 + d2 * d2 + d3 * d3;
#pragma unroll
        for (int o = 16; o > 0; o >>= 1) q += __shfl_xor_sync(0xffffffff, q, o);
        float rsd = rsqrtf(q * (1.f / 128.f) + EPSV);
        int i0 = lane * 4;
        XT[(i0 + 0) * 132 + r] = fmaf(d0 * rsd, s_ln1w[i0 + 0], s_ln1b[i0 + 0]);
        XT[(i0 + 1) * 132 + r] = fmaf(d1 * rsd, s_ln1w[i0 + 1], s_ln1b[i0 + 1]);
        XT[(i0 + 2) * 132 + r] = fmaf(d2 * rsd, s_ln1w[i0 + 2], s_ln1b[i0 + 2]);
        XT[(i0 + 3) * 132 + r] = fmaf(d3 * rsd, s_ln1w[i0 + 3], s_ln1b[i0 + 3]);
    }
    __syncthreads();

    // GEMM1: H[row][o] = relu( sum_k XT[k][row] * W1[k][o] + fc1b[o] )
    int tx = tid & 15;   // o / 8
    int ty = tid >> 4;   // row / 8
    float acc[8][8];
#pragma unroll
    for (int i = 0; i < 8; i++)
#pragma unroll
        for (int j = 0; j < 8; j++) acc[i][j] = 0.f;
#pragma unroll 4
    for (int k = 0; k < 128; k++) {
        float4 a0 = *(const float4*)&XT[k * 132 + ty * 8];
        float4 a1 = *(const float4*)&XT[k * 132 + ty * 8 + 4];
        float4 b0 = *(const float4*)&W1[k * 132 + tx * 8];
        float4 b1 = *(const float4*)&W1[k * 132 + tx * 8 + 4];
        float a[8] = {a0.x, a0.y, a0.z, a0.w, a1.x, a1.y, a1.z, a1.w};
        float b[8] = {b0.x, b0.y, b0.z, b0.w, b1.x, b1.y, b1.z, b1.w};
#pragma unroll
        for (int i = 0; i < 8; i++)
#pragma unroll
            for (int j = 0; j < 8; j++) acc[i][j] = fmaf(a[i], b[j], acc[i][j]);
    }
    __syncthreads();   // all XT reads done; reuse buffer as H[row][132]
    float* H = XT;
#pragma unroll
    for (int i = 0; i < 8; i++) {
        int r = ty * 8 + i;
#pragma unroll
        for (int j = 0; j < 8; j++) {
            int o = tx * 8 + j;
            H[r * 132 + o] = fmaxf(acc[i][j] + s_fc1b[o], 0.f);
        }
    }
    __syncthreads();

    // LN2 in place: warp per row
    for (int it = 0; it < 16; it++) {
        int r = warp + it * 8;
        float4 hv = *(const float4*)&H[r * 132 + lane * 4];
        float s = hv.x + hv.y + hv.z + hv.w;
#pragma unroll
        for (int o = 16; o > 0; o >>= 1) s += __shfl_xor_sync(0xffffffff, s, o);
        float mu = s * (1.f / 128.f);
        float d0 = hv.x - mu, d1 = hv.y - mu, d2 = hv.z - mu, d3 = hv.w - mu;
        float q = d0 * d0 + d1 * d1 + d2 * d2 + d3 * d3;
#pragma unroll
        for (int o = 16; o > 0; o >>= 1) q += __shfl_xor_sync(0xffffffff, q, o);
        float rsd = rsqrtf(q * (1.f / 128.f) + EPSV);
        int i0 = lane * 4;
        float4 nv;
        nv.x = fmaf(d0 * rsd, s_ln2w[i0 + 0], s_ln2b[i0 + 0]);
        nv.y = fmaf(d1 * rsd, s_ln2w[i0 + 1], s_ln2b[i0 + 1]);
        nv.z = fmaf(d2 * rsd, s_ln2w[i0 + 2], s_ln2b[i0 + 2]);
        nv.w = fmaf(d3 * rsd, s_ln2w[i0 + 3], s_ln2b[i0 + 3]);
        *(float4*)&H[r * 132 + lane * 4] = nv;
    }
    __syncthreads();

    // GEMM2: y[row][c] = sum_i H[row][i] * fc2w[i][c] + fc2b[c]; 2 threads/row, 5 cols each
    {
        int r  = tid >> 1;
        int c0 = (tid & 1) * 5;
        float a0 = 0.f, a1 = 0.f, a2 = 0.f, a3 = 0.f, a4 = 0.f;
#pragma unroll 4
        for (int i = 0; i < 128; i++) {
            float hv = H[r * 132 + i];
            const float* wrow = &s_fc2w[i * 10 + c0];
            a0 = fmaf(hv, wrow[0], a0);
            a1 = fmaf(hv, wrow[1], a1);
            a2 = fmaf(hv, wrow[2], a2);
            a3 = fmaf(hv, wrow[3], a3);
            a4 = fmaf(hv, wrow[4], a4);
        }
        size_t R = row0 + r;
        g_Y[R * N_CLASS + c0 + 0] = a0 + s_fc2b[c0 + 0];
        g_Y[R * N_CLASS + c0 + 1] = a1 + s_fc2b[c0 + 1];
        g_Y[R * N_CLASS + c0 + 2] = a2 + s_fc2b[c0 + 2];
        g_Y[R * N_CLASS + c0 + 3] = a3 + s_fc2b[c0 + 3];
        g_Y[R * N_CLASS + c0 + 4] = a4 + s_fc2b[c0 + 4];
    }
}

// =====================================================================
// Kernel 4: out[b][c] = mean over forests of Y[f][b][c]   (fully coalesced)
// =====================================================================
__global__ void k4_reduce(float* __restrict__ out) {
    int i = blockIdx.x * 256 + threadIdx.x;   // i = b*10 + c, exactly the inner layout of Y per f
    if (i < BATCH * N_CLASS) {
        float s = 0.f;
        for (int f = 0; f < N_FOREST; f++)
            s += g_Y[(size_t)f * (BATCH * N_CLASS) + i];
        out[i] = s * (1.f / N_FOREST);
    }
}

// =====================================================================
extern "C" void kernel_launch(void* const* d_in, const int* in_sizes, int n_in,
                              void* d_out, int out_size) {
    const float* x     = (const float*)d_in[0];
    const float* w1    = (const float*)d_in[1];
    const float* b1    = (const float*)d_in[2];
    const int*   perm  = (const int*)  d_in[3];
    const float* gn1w  = (const float*)d_in[4];
    const float* gn1b  = (const float*)d_in[5];
    const float* c2w   = (const float*)d_in[6];
    const float* c2b   = (const float*)d_in[7];
    const float* gn2w  = (const float*)d_in[8];
    const float* gn2b  = (const float*)d_in[9];
    const float* c3w   = (const float*)d_in[10];
    const float* c3b   = (const float*)d_in[11];
    const int*   swr   = (const int*)  d_in[12];
    const float* E     = (const float*)d_in[13];
    const float* ln1w  = (const float*)d_in[14];
    const float* ln1b  = (const float*)d_in[15];
    const float* fc1w  = (const float*)d_in[16];
    const float* fc1b  = (const float*)d_in[17];
    const float* ln2w  = (const float*)d_in[18];
    const float* ln2b  = (const float*)d_in[19];
    const float* fc2w  = (const float*)d_in[20];
    const float* fc2b  = (const float*)d_in[21];
    float* out = (float*)d_out;

    cudaFuncSetAttribute(k2_forest, cudaFuncAttributeMaxDynamicSharedMemorySize, K2_SMEM);
    cudaFuncSetAttribute(k3_mlp,    cudaFuncAttributeMaxDynamicSharedMemorySize, K3_SMEM);

    k0_transpose<<<(N_COL * BATCH) / 256, 256>>>(x);
    k1_rodt<<<dim3(N_RODT, BATCH / 256), 256>>>(w1, b1, perm, gn1w, gn1b,
                                                c2w, c2b, gn2w, gn2b, c3w, c3b);
    k2_forest<<<dim3(BATCH / 128, N_FOREST), 256, K2_SMEM>>>(swr, E);
    k3_mlp<<<(N_FOREST * BATCH) / 128, 256, K3_SMEM>>>(ln1w, ln1b, fc1w, fc1b,
                                                       ln2w, ln2b, fc2w, fc2b);
    k4_reduce<<<(BATCH * N_CLASS + 255) / 256, 256>>>(out);
}

// round 4
// speedup vs baseline: 2.1749x; 2.1749x over previous
#include <cuda_runtime.h>
#include <cuda_bf16.h>
#include <cstdint>

// ---------------- problem constants ----------------
#define BATCH    4096
#define N_COL    100
#define N_COND   64
#define TOTAL    6400
#define N_RODT   1600
#define N_EST    160
#define N_FOREST 100
#define N_HID    128
#define N_CLASS  10
#define EPSV     1e-5f

// ---------------- device scratch ----------------
__device__ float g_xT  [N_COL * BATCH];                       // x transposed [c][b]
__device__ float g_wT  [N_RODT * BATCH];                      // rODT weights [g][b]
__device__ float g_Etf [N_RODT * N_HID];                      // E, tf32-rounded fp32
__device__ float g_W1tf[N_HID * N_HID];                       // fc1w, tf32-rounded fp32 [k][o]
__device__ float g_Y   [(size_t)N_FOREST * BATCH * N_CLASS];  // per-forest logits

__device__ __forceinline__ float to_tf32(float x) {
    uint32_t u;
    asm("cvt.rna.tf32.f32 %0, %1;" : "=r"(u) : "f"(x));
    return __uint_as_float(u);
}

// =====================================================================
// Kernel 0: transpose x [B,100] -> xT [100,B]
// =====================================================================
__global__ void k0_transpose(const float* __restrict__ x) {
    int i = blockIdx.x * 256 + threadIdx.x;
    int c = i >> 12;
    int b = i & 4095;
    g_xT[i] = x[b * N_COL + c];
}

// =====================================================================
// Kernel pre: tf32-round E and fc1w
// =====================================================================
__global__ void k_pre(const float* __restrict__ E, const float* __restrict__ fc1w) {
    int i = blockIdx.x * 256 + threadIdx.x;
    if (i < N_RODT * N_HID) g_Etf[i] = to_tf32(E[i]);
    if (i < N_HID * N_HID)  g_W1tf[i] = to_tf32(fc1w[i]);
}

// =====================================================================
// Kernel 1: condition gen + rODT scoring (validated in R1)
// =====================================================================
__global__ void k1_rodt(const float* __restrict__ w1, const float* __restrict__ b1,
                        const int*   __restrict__ perm,
                        const float* __restrict__ gn1w, const float* __restrict__ gn1b,
                        const float* __restrict__ c2w,  const float* __restrict__ c2b,
                        const float* __restrict__ gn2w, const float* __restrict__ gn2b,
                        const float* __restrict__ c3w,  const float* __restrict__ c3b) {
    int g   = blockIdx.x;
    int tid = threadIdx.x;
    __shared__ int   sc[4];
    __shared__ float sw1[4], sb1[4], sg1w[4], sg1b[4];
    __shared__ float sw2[16], sb2[4], sg2w[4], sg2b[4], sw3[4], sb3;
    if (tid < 4) {
        int t = 4 * g + tid;
        int p = perm[t];
        int c = p % N_COL;
        int j = p / N_COL;
        sc [tid] = c;
        sw1[tid] = w1[c * N_COND + j];
        sb1[tid] = b1[c * N_COND + j];
        sg1w[tid] = gn1w[t];  sg1b[tid] = gn1b[t];
        sb2 [tid] = c2b[t];
        sg2w[tid] = gn2w[t];  sg2b[tid] = gn2b[t];
        sw3 [tid] = c3w[g * 4 + tid];
    }
    if (tid < 16) sw2[tid] = c2w[g * 16 + tid];
    if (tid == 31) sb3 = c3b[g];
    __syncthreads();

    int b = blockIdx.y * 256 + tid;
    float v[4];
#pragma unroll
    for (int k = 0; k < 4; k++) {
        float z = fmaf(g_xT[sc[k] * BATCH + b], sw1[k], sb1[k]);
        v[k] = 1.f / (1.f + __expf(-z));
    }
    float mu = 0.25f * (v[0] + v[1] + v[2] + v[3]);
    float var = 0.f;
#pragma unroll
    for (int k = 0; k < 4; k++) { float d = v[k] - mu; var += d * d; }
    var *= 0.25f;
    float rs = rsqrtf(var + EPSV);
    float n[4];
#pragma unroll
    for (int k = 0; k < 4; k++) n[k] = fmaf((v[k] - mu) * rs, sg1w[k], sg1b[k]);
    float h[4];
#pragma unroll
    for (int o = 0; o < 4; o++) {
        float a = sb2[o];
#pragma unroll
        for (int k = 0; k < 4; k++) a = fmaf(n[k], sw2[k * 4 + o], a);
        h[o] = fmaxf(a, 0.f);
    }
    float mu2 = 0.25f * (h[0] + h[1] + h[2] + h[3]);
    float var2 = 0.f;
#pragma unroll
    for (int k = 0; k < 4; k++) { float d = h[k] - mu2; var2 += d * d; }
    var2 *= 0.25f;
    float rs2 = rsqrtf(var2 + EPSV);
    float wo = sb3;
#pragma unroll
    for (int k = 0; k < 4; k++)
        wo = fmaf(fmaf((h[k] - mu2) * rs2, sg2w[k], sg2b[k]), sw3[k], wo);
    g_wT[(size_t)g * BATCH + b] = wo;
}

// =====================================================================
// tf32 mma m16n8k8 helpers
// =====================================================================
__device__ __forceinline__ void mma_tf32(float* c, const uint32_t* a, const uint32_t* b) {
    asm volatile("mma.sync.aligned.m16n8k8.row.col.f32.tf32.tf32.f32 "
                 "{%0,%1,%2,%3}, {%4,%5,%6,%7}, {%8,%9}, {%0,%1,%2,%3};"
                 : "+f"(c[0]), "+f"(c[1]), "+f"(c[2]), "+f"(c[3])
                 : "r"(a[0]), "r"(a[1]), "r"(a[2]), "r"(a[3]), "r"(b[0]), "r"(b[1]));
}

// C^T[m][n] += A^T B with Asm[k][136] (cols=m), Bsm[k][136] (cols=n), fp32/tf32.
// 8 warps: wm = warp&3 (M=32 each), wn = warp>>2 (N=64 each).
// Fragment LDS banks: (8t + g) mod 32 -> conflict-free.
template<int KSTEPS>
__device__ __forceinline__ void gemm_tf32(const float* __restrict__ Asm,
                                          const float* __restrict__ Bsm,
                                          int warp, int lane, float acc[2][8][4]) {
    const int wm = warp & 3, wn = warp >> 2;
    const int M0 = wm * 32, N0 = wn * 64;
    const int g = lane >> 2, t = lane & 3;
#pragma unroll
    for (int ks = 0; ks < KSTEPS; ks++) {
        const int k0 = ks * 8;
        uint32_t a[2][4];
#pragma unroll
        for (int mt = 0; mt < 2; mt++) {
            const float* base = Asm + (k0 + t) * 136 + M0 + mt * 16 + g;
            a[mt][0] = __float_as_uint(base[0]);
            a[mt][1] = __float_as_uint(base[8]);
            a[mt][2] = __float_as_uint(base[4 * 136]);
            a[mt][3] = __float_as_uint(base[4 * 136 + 8]);
        }
        uint32_t bf[8][2];
#pragma unroll
        for (int nt = 0; nt < 8; nt++) {
            const float* base = Bsm + (k0 + t) * 136 + N0 + nt * 8 + g;
            bf[nt][0] = __float_as_uint(base[0]);
            bf[nt][1] = __float_as_uint(base[4 * 136]);
        }
#pragma unroll
        for (int mt = 0; mt < 2; mt++)
#pragma unroll
            for (int nt = 0; nt < 8; nt++) mma_tf32(acc[mt][nt], a[mt], bf[nt]);
    }
}

// LayerNorm over d (rows, 128) per column; write tf32-rounded fp32 to Y (stride 136)
__device__ __forceinline__ void ln_to_tf32(const float* X, float* Y,
                                           const float* w, const float* bb,
                                           int tid, float* red) {
    const int col = tid & 127, half = tid >> 7, d0 = half * 64;
    float s = 0.f;
    for (int d = d0; d < d0 + 64; d++) s += X[d * 132 + col];
    red[half * 128 + col] = s;
    __syncthreads();
    const float mu = (red[col] + red[128 + col]) * (1.f / 128.f);
    __syncthreads();
    float q = 0.f;
    for (int d = d0; d < d0 + 64; d++) { float v = X[d * 132 + col] - mu; q += v * v; }
    red[half * 128 + col] = q;
    __syncthreads();
    const float rs = rsqrtf((red[col] + red[128 + col]) * (1.f / 128.f) + EPSV);
    for (int d = d0; d < d0 + 64; d++) {
        float v = (X[d * 132 + col] - mu) * rs;
        Y[d * 136 + col] = to_tf32(fmaf(v, w[d], bb[d]));
    }
}

// LayerNorm in place (stride 132 fp32)
__device__ __forceinline__ void ln_inplace(float* X, const float* w, const float* bb,
                                           int tid, float* red) {
    const int col = tid & 127, half = tid >> 7, d0 = half * 64;
    float s = 0.f;
    for (int d = d0; d < d0 + 64; d++) s += X[d * 132 + col];
    red[half * 128 + col] = s;
    __syncthreads();
    const float mu = (red[col] + red[128 + col]) * (1.f / 128.f);
    __syncthreads();
    float q = 0.f;
    for (int d = d0; d < d0 + 64; d++) { float v = X[d * 132 + col] - mu; q += v * v; }
    red[half * 128 + col] = q;
    __syncthreads();
    const float rs = rsqrtf((red[col] + red[128 + col]) * (1.f / 128.f) + EPSV);
    for (int d = d0; d < d0 + 64; d++) {
        float v = (X[d * 132 + col] - mu) * rs;
        X[d * 132 + col] = fmaf(v, w[d], bb[d]);
    }
}

// =====================================================================
// Kernel 23 (tf32): per-(forest f, 128 b's):
//  P=exp(w); invS = 1/colsum(P); C^T = (E^T P)*invS; LN1 -> Xn;
//  H^T = W1^T Xn + b, relu; LN2; fc2 -> g_Y
// smem (dynamic): Csm f32 [128][132] = 67584
//                 Pf  f32 [160][136] = 87040   (P, then Xn rows 0..127)
//                 Wb  f32 [ 80][136] = 43520   (E halves / W1 halves)
// total dynamic 198144 + ~10KB static < 227KB limit
// =====================================================================
#define K23_SMEM (67584 + 87040 + 43520)
__global__ void __launch_bounds__(256) k23_forest_mlp(
        const int* __restrict__ swr,
        const float* __restrict__ ln1w, const float* __restrict__ ln1b,
        const float* __restrict__ fc1b,
        const float* __restrict__ ln2w, const float* __restrict__ ln2b,
        const float* __restrict__ fc2w, const float* __restrict__ fc2b) {
    extern __shared__ char sh[];
    float* Csm = (float*)sh;                     // [128][132]
    float* Pf  = (float*)(sh + 67584);           // [160][136]
    float* Wb  = (float*)(sh + 67584 + 87040);   // [80][136]

    __shared__ int   s_idx[160];
    __shared__ float s_ln1w[128], s_ln1b[128], s_fc1b[128], s_ln2w[128], s_ln2b[128];
    __shared__ float s_fc2w[1280], s_fc2b[10];
    __shared__ float s_red[256];
    __shared__ float s_invS[128];

    const int tid = threadIdx.x, lane = tid & 31, warp = tid >> 5;
    const int f = blockIdx.y;
    const int b0 = blockIdx.x * 128;

    if (tid < 160) s_idx[tid] = swr[f * N_EST + tid];
    if (tid < 128) {
        s_ln1w[tid] = ln1w[tid]; s_ln1b[tid] = ln1b[tid];
        s_fc1b[tid] = fc1b[tid];
        s_ln2w[tid] = ln2w[tid]; s_ln2b[tid] = ln2b[tid];
    }
    for (int i = tid; i < 1280; i += 256) s_fc2w[i] = fc2w[i];
    if (tid < 10) s_fc2b[tid] = fc2b[tid];
    __syncthreads();

    // --- Stage A: P = tf32(exp(w)) gathered ---
#pragma unroll 2
    for (int i = tid; i < 160 * 32; i += 256) {
        int e = i >> 5, b4 = i & 31;
        float4 v = *(const float4*)(g_wT + (size_t)s_idx[e] * BATCH + b0 + b4 * 4);
        float* dst = Pf + e * 136 + b4 * 4;
        dst[0] = to_tf32(__expf(v.x));
        dst[1] = to_tf32(__expf(v.y));
        dst[2] = to_tf32(__expf(v.z));
        dst[3] = to_tf32(__expf(v.w));
    }
    __syncthreads();

    // --- invS + stage E half 0 ---
    if (tid < 128) {
        float s = 0.f;
        for (int e = 0; e < 160; e++) s += Pf[e * 136 + tid];
        s_invS[tid] = 1.f / s;
    }
#pragma unroll 2
    for (int i = tid; i < 80 * 32; i += 256) {
        int e = i >> 5, q = i & 31;
        *(float4*)(Wb + e * 136 + q * 4) =
            *(const float4*)(g_Etf + (size_t)s_idx[e] * N_HID + q * 4);
    }
    __syncthreads();

    // --- GEMM A (K=160 in two halves of 80) ---
    float acc[2][8][4];
#pragma unroll
    for (int mt = 0; mt < 2; mt++)
#pragma unroll
        for (int nt = 0; nt < 8; nt++)
#pragma unroll
            for (int r = 0; r < 4; r++) acc[mt][nt][r] = 0.f;
    gemm_tf32<10>(Wb, Pf, warp, lane, acc);
    __syncthreads();
#pragma unroll 2
    for (int i = tid; i < 80 * 32; i += 256) {
        int e = i >> 5, q = i & 31;
        *(float4*)(Wb + e * 136 + q * 4) =
            *(const float4*)(g_Etf + (size_t)s_idx[80 + e] * N_HID + q * 4);
    }
    __syncthreads();
    gemm_tf32<10>(Wb, Pf + 80 * 136, warp, lane, acc);

    // epilogue: scale by invS, store C^T to Csm
    {
        const int wm = warp & 3, wn = warp >> 2, g = lane >> 2, q2 = (lane & 3) * 2;
#pragma unroll
        for (int mt = 0; mt < 2; mt++)
#pragma unroll
            for (int nt = 0; nt < 8; nt++) {
                int row = wm * 32 + mt * 16 + g, col = wn * 64 + nt * 8 + q2;
                float i0 = s_invS[col], i1 = s_invS[col + 1];
                *(float2*)&Csm[row * 132 + col] =
                    make_float2(acc[mt][nt][0] * i0, acc[mt][nt][1] * i1);
                *(float2*)&Csm[(row + 8) * 132 + col] =
                    make_float2(acc[mt][nt][2] * i0, acc[mt][nt][3] * i1);
            }
    }
    __syncthreads();

    // --- LN1 -> Xn (tf32) into Pf rows 0..127; stage W1 half 0 into Wb ---
    ln_to_tf32(Csm, Pf, s_ln1w, s_ln1b, tid, s_red);
#pragma unroll 2
    for (int i = tid; i < 64 * 32; i += 256) {
        int k = i >> 5, q = i & 31;
        *(float4*)(Wb + k * 136 + q * 4) = ((const float4*)g_W1tf)[k * 32 + q];
    }
    __syncthreads();

    // --- GEMM B: H^T[o][b] = sum_k W1[k][o]*Xn[k][b], K=128 in two halves of 64 ---
#pragma unroll
    for (int mt = 0; mt < 2; mt++)
#pragma unroll
        for (int nt = 0; nt < 8; nt++)
#pragma unroll
            for (int r = 0; r < 4; r++) acc[mt][nt][r] = 0.f;
    gemm_tf32<8>(Wb, Pf, warp, lane, acc);
    __syncthreads();
#pragma unroll 2
    for (int i = tid; i < 64 * 32; i += 256) {
        int k = i >> 5, q = i & 31;
        *(float4*)(Wb + k * 136 + q * 4) = ((const float4*)g_W1tf)[(64 + k) * 32 + q];
    }
    __syncthreads();
    gemm_tf32<8>(Wb, Pf + 64 * 136, warp, lane, acc);
    {
        const int wm = warp & 3, wn = warp >> 2, g = lane >> 2, q2 = (lane & 3) * 2;
#pragma unroll
        for (int mt = 0; mt < 2; mt++)
#pragma unroll
            for (int nt = 0; nt < 8; nt++) {
                int row = wm * 32 + mt * 16 + g, col = wn * 64 + nt * 8 + q2;
                float bia = s_fc1b[row], bib = s_fc1b[row + 8];
                *(float2*)&Csm[row * 132 + col] =
                    make_float2(fmaxf(acc[mt][nt][0] + bia, 0.f), fmaxf(acc[mt][nt][1] + bia, 0.f));
                *(float2*)&Csm[(row + 8) * 132 + col] =
                    make_float2(fmaxf(acc[mt][nt][2] + bib, 0.f), fmaxf(acc[mt][nt][3] + bib, 0.f));
            }
    }
    __syncthreads();

    // --- LN2 in place ---
    ln_inplace(Csm, s_ln2w, s_ln2b, tid, s_red);
    __syncthreads();

    // --- fc2 ---
    {
        const int b  = tid >> 1;
        const int c0 = (tid & 1) * 5;
        float a0 = 0.f, a1 = 0.f, a2 = 0.f, a3 = 0.f, a4 = 0.f;
#pragma unroll 4
        for (int o = 0; o < 128; o++) {
            float hv = Csm[o * 132 + b];
            const float* wr = &s_fc2w[o * 10 + c0];
            a0 = fmaf(hv, wr[0], a0);
            a1 = fmaf(hv, wr[1], a1);
            a2 = fmaf(hv, wr[2], a2);
            a3 = fmaf(hv, wr[3], a3);
            a4 = fmaf(hv, wr[4], a4);
        }
        size_t R = (size_t)f * BATCH + b0 + b;
        g_Y[R * N_CLASS + c0 + 0] = a0 + s_fc2b[c0 + 0];
        g_Y[R * N_CLASS + c0 + 1] = a1 + s_fc2b[c0 + 1];
        g_Y[R * N_CLASS + c0 + 2] = a2 + s_fc2b[c0 + 2];
        g_Y[R * N_CLASS + c0 + 3] = a3 + s_fc2b[c0 + 3];
        g_Y[R * N_CLASS + c0 + 4] = a4 + s_fc2b[c0 + 4];
    }
}

// =====================================================================
// Kernel 4: out[b][c] = mean over forests
// =====================================================================
__global__ void k4_reduce(float* __restrict__ out) {
    int i = blockIdx.x * 256 + threadIdx.x;
    if (i < BATCH * N_CLASS) {
        float s = 0.f;
        for (int f = 0; f < N_FOREST; f++)
            s += g_Y[(size_t)f * (BATCH * N_CLASS) + i];
        out[i] = s * (1.f / N_FOREST);
    }
}

// =====================================================================
extern "C" void kernel_launch(void* const* d_in, const int* in_sizes, int n_in,
                              void* d_out, int out_size) {
    const float* x     = (const float*)d_in[0];
    const float* w1    = (const float*)d_in[1];
    const float* b1    = (const float*)d_in[2];
    const int*   perm  = (const int*)  d_in[3];
    const float* gn1w  = (const float*)d_in[4];
    const float* gn1b  = (const float*)d_in[5];
    const float* c2w   = (const float*)d_in[6];
    const float* c2b   = (const float*)d_in[7];
    const float* gn2w  = (const float*)d_in[8];
    const float* gn2b  = (const float*)d_in[9];
    const float* c3w   = (const float*)d_in[10];
    const float* c3b   = (const float*)d_in[11];
    const int*   swr   = (const int*)  d_in[12];
    const float* E     = (const float*)d_in[13];
    const float* ln1w  = (const float*)d_in[14];
    const float* ln1b  = (const float*)d_in[15];
    const float* fc1w  = (const float*)d_in[16];
    const float* fc1b  = (const float*)d_in[17];
    const float* ln2w  = (const float*)d_in[18];
    const float* ln2b  = (const float*)d_in[19];
    const float* fc2w  = (const float*)d_in[20];
    const float* fc2b  = (const float*)d_in[21];
    float* out = (float*)d_out;

    cudaFuncSetAttribute(k23_forest_mlp, cudaFuncAttributeMaxDynamicSharedMemorySize, K23_SMEM);

    k0_transpose<<<(N_COL * BATCH) / 256, 256>>>(x);
    k_pre<<<(N_RODT * N_HID + 255) / 256, 256>>>(E, fc1w);
    k1_rodt<<<dim3(N_RODT, BATCH / 256), 256>>>(w1, b1, perm, gn1w, gn1b,
                                                c2w, c2b, gn2w, gn2b, c3w, c3b);
    k23_forest_mlp<<<dim3(BATCH / 128, N_FOREST), 256, K23_SMEM>>>(
        swr, ln1w, ln1b, fc1b, ln2w, ln2b, fc2w, fc2b);
    k4_reduce<<<(BATCH * N_CLASS + 255) / 256, 256>>>(out);
}

// round 5
// speedup vs baseline: 3.3140x; 1.5238x over previous
#include <cuda_runtime.h>
#include <cuda_bf16.h>
#include <cstdint>

// ---------------- problem constants ----------------
#define BATCH    4096
#define N_COL    100
#define N_COND   64
#define TOTAL    6400
#define N_RODT   1600
#define N_EST    160
#define N_FOREST 100
#define N_HID    128
#define N_CLASS  10
#define EPSV     1e-5f
#define SDIM     136      // smem row stride (floats); 136 mod 32 == 8 -> conflict-free frags

// ---------------- device scratch ----------------
__device__ float g_xT [N_COL * BATCH];
__device__ float g_wT [N_RODT * BATCH];
__device__ float g_Etf[N_RODT * N_HID];                      // tf32(E)
__device__ float g_W1p[N_HID * N_HID];                       // tf32(fc1w * ln1w) [d][o]
__device__ float g_wc2[N_HID * 12];                          // tf32(fc2w * ln2w) [o][12] (10 used)
__device__ float g_s1[N_HID], g_d1[N_HID];                   // colsum(W1p); fc1b + W1^T ln1b
__device__ float g_s2[16],    g_d2[16];                      // colsum(wc2); fc2b + w2^T ln2b
__device__ float g_Y  [(size_t)N_FOREST * BATCH * N_CLASS];

__device__ __forceinline__ float to_tf32(float x) {
    uint32_t u;
    asm("cvt.rna.tf32.f32 %0, %1;" : "=r"(u) : "f"(x));
    return __uint_as_float(u);
}
__device__ __forceinline__ void cpasync16(uint32_t dst, const void* src) {
    asm volatile("cp.async.cg.shared.global [%0], [%1], 16;" :: "r"(dst), "l"(src));
}
#define CP_COMMIT asm volatile("cp.async.commit_group;")
#define CP_WAIT0  asm volatile("cp.async.wait_group 0;")

// =====================================================================
// Kernel 0: transpose x
// =====================================================================
__global__ void k0_transpose(const float* __restrict__ x) {
    int i = blockIdx.x * 256 + threadIdx.x;
    int c = i >> 12;
    int b = i & 4095;
    g_xT[i] = x[b * N_COL + c];
}

// =====================================================================
// k_pre: tf32-round E; build W1' = fc1w*ln1w, wc2 = fc2w*ln2w
// =====================================================================
__global__ void k_pre(const float* __restrict__ E, const float* __restrict__ fc1w,
                      const float* __restrict__ ln1w, const float* __restrict__ fc2w,
                      const float* __restrict__ ln2w) {
    int i = blockIdx.x * 256 + threadIdx.x;
    if (i < N_RODT * N_HID) g_Etf[i] = to_tf32(E[i]);
    if (i < N_HID * N_HID) {
        int d = i >> 7;
        g_W1p[i] = to_tf32(fc1w[i] * ln1w[d]);
    }
    if (i < N_HID * 12) {
        int o = i / 12, c = i % 12;
        g_wc2[i] = (c < 10) ? to_tf32(fc2w[o * 10 + c] * ln2w[o]) : 0.f;
    }
}
// column sums / bias folds (1 block, 128 threads)
__global__ void k_pre2(const float* __restrict__ fc1w, const float* __restrict__ fc1b,
                       const float* __restrict__ ln1b, const float* __restrict__ fc2w,
                       const float* __restrict__ fc2b, const float* __restrict__ ln2b) {
    int o = threadIdx.x;
    float s = 0.f, d = 0.f;
    for (int k = 0; k < 128; k++) {
        s += g_W1p[k * 128 + o];
        d += fc1w[k * 128 + o] * ln1b[k];
    }
    g_s1[o] = s;
    g_d1[o] = d + fc1b[o];
    if (o < 10) {
        float s2 = 0.f, d2 = 0.f;
        for (int k = 0; k < 128; k++) {
            s2 += g_wc2[k * 12 + o];
            d2 += ln2b[k] * fc2w[k * 10 + o];
        }
        g_s2[o] = s2;
        g_d2[o] = d2 + fc2b[o];
    } else if (o < 16) {
        g_s2[o] = 0.f; g_d2[o] = 0.f;
    }
}

// =====================================================================
// Kernel 1: condition gen + rODT scoring (validated)
// =====================================================================
__global__ void k1_rodt(const float* __restrict__ w1, const float* __restrict__ b1,
                        const int*   __restrict__ perm,
                        const float* __restrict__ gn1w, const float* __restrict__ gn1b,
                        const float* __restrict__ c2w,  const float* __restrict__ c2b,
                        const float* __restrict__ gn2w, const float* __restrict__ gn2b,
                        const float* __restrict__ c3w,  const float* __restrict__ c3b) {
    int g   = blockIdx.x;
    int tid = threadIdx.x;
    __shared__ int   sc[4];
    __shared__ float sw1[4], sb1[4], sg1w[4], sg1b[4];
    __shared__ float sw2[16], sb2[4], sg2w[4], sg2b[4], sw3[4], sb3;
    if (tid < 4) {
        int t = 4 * g + tid;
        int p = perm[t];
        int c = p % N_COL;
        int j = p / N_COL;
        sc [tid] = c;
        sw1[tid] = w1[c * N_COND + j];
        sb1[tid] = b1[c * N_COND + j];
        sg1w[tid] = gn1w[t];  sg1b[tid] = gn1b[t];
        sb2 [tid] = c2b[t];
        sg2w[tid] = gn2w[t];  sg2b[tid] = gn2b[t];
        sw3 [tid] = c3w[g * 4 + tid];
    }
    if (tid < 16) sw2[tid] = c2w[g * 16 + tid];
    if (tid == 31) sb3 = c3b[g];
    __syncthreads();

    int b = blockIdx.y * 256 + tid;
    float v[4];
#pragma unroll
    for (int k = 0; k < 4; k++) {
        float z = fmaf(g_xT[sc[k] * BATCH + b], sw1[k], sb1[k]);
        v[k] = 1.f / (1.f + __expf(-z));
    }
    float mu = 0.25f * (v[0] + v[1] + v[2] + v[3]);
    float var = 0.f;
#pragma unroll
    for (int k = 0; k < 4; k++) { float d = v[k] - mu; var += d * d; }
    var *= 0.25f;
    float rs = rsqrtf(var + EPSV);
    float n[4];
#pragma unroll
    for (int k = 0; k < 4; k++) n[k] = fmaf((v[k] - mu) * rs, sg1w[k], sg1b[k]);
    float h[4];
#pragma unroll
    for (int o = 0; o < 4; o++) {
        float a = sb2[o];
#pragma unroll
        for (int k = 0; k < 4; k++) a = fmaf(n[k], sw2[k * 4 + o], a);
        h[o] = fmaxf(a, 0.f);
    }
    float mu2 = 0.25f * (h[0] + h[1] + h[2] + h[3]);
    float var2 = 0.f;
#pragma unroll
    for (int k = 0; k < 4; k++) { float d = h[k] - mu2; var2 += d * d; }
    var2 *= 0.25f;
    float rs2 = rsqrtf(var2 + EPSV);
    float wo = sb3;
#pragma unroll
    for (int k = 0; k < 4; k++)
        wo = fmaf(fmaf((h[k] - mu2) * rs2, sg2w[k], sg2b[k]), sw3[k], wo);
    g_wT[(size_t)g * BATCH + b] = wo;
}

// =====================================================================
// tf32 m16n8k8 mma
// =====================================================================
__device__ __forceinline__ void mma_tf32(float* c, const uint32_t* a, const uint32_t* b) {
    asm volatile("mma.sync.aligned.m16n8k8.row.col.f32.tf32.tf32.f32 "
                 "{%0,%1,%2,%3}, {%4,%5,%6,%7}, {%8,%9}, {%0,%1,%2,%3};"
                 : "+f"(c[0]), "+f"(c[1]), "+f"(c[2]), "+f"(c[3])
                 : "r"(a[0]), "r"(a[1]), "r"(a[2]), "r"(a[3]), "r"(b[0]), "r"(b[1]));
}

// 16 warps, 32x32 warp tiles over 128x128. Asm/Bsm k-major, stride SDIM.
template<int KSTEPS>
__device__ __forceinline__ void gemm512(const float* __restrict__ Asm,
                                        const float* __restrict__ Bsm,
                                        int warp, int lane, float acc[2][4][4]) {
    const int M0 = (warp & 3) * 32, N0 = (warp >> 2) * 32;
    const int g = lane >> 2, t = lane & 3;
#pragma unroll
    for (int ks = 0; ks < KSTEPS; ks++) {
        const int k0 = ks * 8;
        const float* ab = Asm + (k0 + t) * SDIM + M0 + g;
        uint32_t a[2][4];
        a[0][0] = __float_as_uint(ab[0]);
        a[0][1] = __float_as_uint(ab[8]);
        a[0][2] = __float_as_uint(ab[4 * SDIM]);
        a[0][3] = __float_as_uint(ab[4 * SDIM + 8]);
        a[1][0] = __float_as_uint(ab[16]);
        a[1][1] = __float_as_uint(ab[24]);
        a[1][2] = __float_as_uint(ab[4 * SDIM + 16]);
        a[1][3] = __float_as_uint(ab[4 * SDIM + 24]);
        const float* bb = Bsm + (k0 + t) * SDIM + N0 + g;
        uint32_t bf[4][2];
#pragma unroll
        for (int nt = 0; nt < 4; nt++) {
            bf[nt][0] = __float_as_uint(bb[nt * 8]);
            bf[nt][1] = __float_as_uint(bb[nt * 8 + 4 * SDIM]);
        }
#pragma unroll
        for (int mt = 0; mt < 2; mt++)
#pragma unroll
            for (int nt = 0; nt < 4; nt++) mma_tf32(acc[mt][nt], a[mt], bf[nt]);
    }
}

// =====================================================================
// k23: fused forest GEMM + MLP with LN folded into GEMM weights.
// dynamic smem: Pf[160][136] (P -> C~ -> H), Wb0[80][136], Wb1[80][136]
// =====================================================================
#define K23_SMEM ((160 * SDIM + 80 * SDIM + 80 * SDIM) * 4)   // 174080
__global__ void __launch_bounds__(512, 1) k23_forest_mlp(const int* __restrict__ swr) {
    extern __shared__ char sh[];
    float* Pf  = (float*)sh;                                // [160][136]
    float* Wb0 = (float*)(sh + 160 * SDIM * 4);             // [80][136]
    float* Wb1 = (float*)(sh + (160 + 80) * SDIM * 4);      // [80][136]

    __shared__ int   s_idx[160];
    __shared__ float s_invS[128];
    __shared__ float s_redA[512], s_redB[512];
    __shared__ float s_mu[128], s_rs[128];
    __shared__ float s_s1[128], s_d1[128];
    __shared__ __align__(16) float s_wc2[128 * 12];
    __shared__ float s_s2[16], s_d2[16];

    const int tid = threadIdx.x, lane = tid & 31, warp = tid >> 5;
    const int f = blockIdx.y;
    const int b0 = blockIdx.x * 128;

    if (tid < 160) s_idx[tid] = swr[f * N_EST + tid];
    __syncthreads();

    // ---- issue E half0 via cp.async ----
    {
        uint32_t wb0 = (uint32_t)__cvta_generic_to_shared(Wb0);
#pragma unroll
        for (int i = tid; i < 80 * 32; i += 512) {
            int e = i >> 5, q = i & 31;
            cpasync16(wb0 + (e * SDIM + q * 4) * 4, g_Etf + (size_t)s_idx[e] * N_HID + q * 4);
        }
        CP_COMMIT;
    }

    // ---- stage P = tf32(exp(w)); load params ----
#pragma unroll
    for (int i = tid; i < 160 * 32; i += 512) {
        int e = i >> 5, b4 = i & 31;
        float4 v = *(const float4*)(g_wT + (size_t)s_idx[e] * BATCH + b0 + b4 * 4);
        float* dst = Pf + e * SDIM + b4 * 4;
        dst[0] = to_tf32(__expf(v.x));
        dst[1] = to_tf32(__expf(v.y));
        dst[2] = to_tf32(__expf(v.z));
        dst[3] = to_tf32(__expf(v.w));
    }
    if (tid < 128) { s_s1[tid] = g_s1[tid]; s_d1[tid] = g_d1[tid]; }
    for (int i = tid; i < 1536; i += 512) s_wc2[i] = g_wc2[i];
    if (tid < 16) { s_s2[tid] = g_s2[tid]; s_d2[tid] = g_d2[tid]; }
    CP_WAIT0;
    __syncthreads();

    // ---- issue E half1 -> Wb1 ----
    {
        uint32_t wb1 = (uint32_t)__cvta_generic_to_shared(Wb1);
#pragma unroll
        for (int i = tid; i < 80 * 32; i += 512) {
            int e = i >> 5, q = i & 31;
            cpasync16(wb1 + (e * SDIM + q * 4) * 4, g_Etf + (size_t)s_idx[80 + e] * N_HID + q * 4);
        }
        CP_COMMIT;
    }

    // ---- invS: column sums of P (160 rows) ----
    {
        const int col = tid & 127, q = tid >> 7;
        float s = 0.f;
        for (int r = 0; r < 40; r++) s += Pf[(q * 40 + r) * SDIM + col];
        s_redA[q * 128 + col] = s;
    }
    __syncthreads();
    if (tid < 128)
        s_invS[tid] = 1.f / (s_redA[tid] + s_redA[128 + tid] + s_redA[256 + tid] + s_redA[384 + tid]);

    // ---- GEMM A: C^T[d][b] = sum_e E[e][d] P[e][b], K=160, two halves ----
    float acc[2][4][4];
#pragma unroll
    for (int mt = 0; mt < 2; mt++)
#pragma unroll
        for (int nt = 0; nt < 4; nt++)
#pragma unroll
            for (int r = 0; r < 4; r++) acc[mt][nt][r] = 0.f;
    gemm512<10>(Wb0, Pf, warp, lane, acc);
    CP_WAIT0;
    __syncthreads();
    // prefetch W1' half0 into Wb0 (Wb0 free now)
    {
        uint32_t wb0 = (uint32_t)__cvta_generic_to_shared(Wb0);
#pragma unroll
        for (int i = tid; i < 64 * 32; i += 512) {
            int k = i >> 5, q = i & 31;
            cpasync16(wb0 + (k * SDIM + q * 4) * 4, g_W1p + k * N_HID + q * 4);
        }
        CP_COMMIT;
    }
    gemm512<10>(Wb1, Pf + 80 * SDIM, warp, lane, acc);
    __syncthreads();   // all P reads done before overwrite
    // prefetch W1' half1 into Wb1
    {
        uint32_t wb1 = (uint32_t)__cvta_generic_to_shared(Wb1);
#pragma unroll
        for (int i = tid; i < 64 * 32; i += 512) {
            int k = i >> 5, q = i & 31;
            cpasync16(wb1 + (k * SDIM + q * 4) * 4, g_W1p + (64 + k) * N_HID + q * 4);
        }
        CP_COMMIT;
    }
    // epilogue A: C~ = tf32(acc * invS) -> Pf rows 0..127
    {
        const int M0 = (warp & 3) * 32, N0 = (warp >> 2) * 32;
        const int g = lane >> 2, q2 = (lane & 3) * 2;
#pragma unroll
        for (int mt = 0; mt < 2; mt++)
#pragma unroll
            for (int nt = 0; nt < 4; nt++) {
                int row = M0 + mt * 16 + g, col = N0 + nt * 8 + q2;
                float i0 = s_invS[col], i1 = s_invS[col + 1];
                Pf[row * SDIM + col]           = to_tf32(acc[mt][nt][0] * i0);
                Pf[row * SDIM + col + 1]       = to_tf32(acc[mt][nt][1] * i1);
                Pf[(row + 8) * SDIM + col]     = to_tf32(acc[mt][nt][2] * i0);
                Pf[(row + 8) * SDIM + col + 1] = to_tf32(acc[mt][nt][3] * i1);
            }
    }
    CP_WAIT0;
    __syncthreads();

    // ---- stats1: per-column mean/rstd of C~ ----
    {
        const int col = tid & 127, q = tid >> 7;
        float s = 0.f, s2 = 0.f;
        for (int r = 0; r < 32; r++) {
            float v = Pf[(q * 32 + r) * SDIM + col];
            s += v; s2 += v * v;
        }
        s_redA[q * 128 + col] = s;
        s_redB[q * 128 + col] = s2;
    }
    __syncthreads();
    if (tid < 128) {
        float s  = s_redA[tid] + s_redA[128 + tid] + s_redA[256 + tid] + s_redA[384 + tid];
        float s2 = s_redB[tid] + s_redB[128 + tid] + s_redB[256 + tid] + s_redB[384 + tid];
        float mu = s * (1.f / 128.f);
        float var = fmaxf(s2 * (1.f / 128.f) - mu * mu, 0.f);
        s_mu[tid] = mu;
        s_rs[tid] = rsqrtf(var + EPSV);
    }
    __syncthreads();

    // ---- GEMM B: G[o][b] = sum_d W1'[d][o] C~[d][b], K=128, two halves ----
#pragma unroll
    for (int mt = 0; mt < 2; mt++)
#pragma unroll
        for (int nt = 0; nt < 4; nt++)
#pragma unroll
            for (int r = 0; r < 4; r++) acc[mt][nt][r] = 0.f;
    gemm512<8>(Wb0, Pf, warp, lane, acc);
    __syncthreads();
    gemm512<8>(Wb1, Pf + 64 * SDIM, warp, lane, acc);
    __syncthreads();   // all C~ reads done before overwrite
    // epilogue B: H = relu(rs_b*(G - mu_b*s1[o]) + d1[o]) -> Pf rows 0..127 (fp32)
    {
        const int M0 = (warp & 3) * 32, N0 = (warp >> 2) * 32;
        const int g = lane >> 2, q2 = (lane & 3) * 2;
#pragma unroll
        for (int mt = 0; mt < 2; mt++)
#pragma unroll
            for (int nt = 0; nt < 4; nt++) {
                int row = M0 + mt * 16 + g, col = N0 + nt * 8 + q2;
                float s1a = s_s1[row], d1a = s_d1[row];
                float s1b = s_s1[row + 8], d1b = s_d1[row + 8];
                float mu0 = s_mu[col], rs0 = s_rs[col];
                float mu1 = s_mu[col + 1], rs1 = s_rs[col + 1];
                Pf[row * SDIM + col]           = fmaxf(fmaf(rs0, acc[mt][nt][0] - mu0 * s1a, d1a), 0.f);
                Pf[row * SDIM + col + 1]       = fmaxf(fmaf(rs1, acc[mt][nt][1] - mu1 * s1a, d1a), 0.f);
                Pf[(row + 8) * SDIM + col]     = fmaxf(fmaf(rs0, acc[mt][nt][2] - mu0 * s1b, d1b), 0.f);
                Pf[(row + 8) * SDIM + col + 1] = fmaxf(fmaf(rs1, acc[mt][nt][3] - mu1 * s1b, d1b), 0.f);
            }
    }
    __syncthreads();

    // ---- stats2: per-column mean/rstd of H ----
    {
        const int col = tid & 127, q = tid >> 7;
        float s = 0.f, s2 = 0.f;
        for (int r = 0; r < 32; r++) {
            float v = Pf[(q * 32 + r) * SDIM + col];
            s += v; s2 += v * v;
        }
        s_redA[q * 128 + col] = s;
        s_redB[q * 128 + col] = s2;
    }
    __syncthreads();
    if (tid < 128) {
        float s  = s_redA[tid] + s_redA[128 + tid] + s_redA[256 + tid] + s_redA[384 + tid];
        float s2 = s_redB[tid] + s_redB[128 + tid] + s_redB[256 + tid] + s_redB[384 + tid];
        float mu = s * (1.f / 128.f);
        float var = fmaxf(s2 * (1.f / 128.f) - mu * mu, 0.f);
        s_mu[tid] = mu;
        s_rs[tid] = rsqrtf(var + EPSV);
    }
    __syncthreads();

    // ---- fc2 (fused LN2): y[b][c] = rs2_b*(S1[b][c] - mu2_b*s2[c]) + d2[c] ----
    {
        const int b = tid >> 2, q = tid & 3;
        float a10[10];
#pragma unroll
        for (int c = 0; c < 10; c++) a10[c] = 0.f;
#pragma unroll 4
        for (int i = 0; i < 32; i++) {
            int o = 4 * i + q;
            float h = Pf[o * SDIM + b];
            const float* wr = s_wc2 + o * 12;
            float4 w0 = *(const float4*)wr;
            float4 w1 = *(const float4*)(wr + 4);
            float2 w2 = *(const float2*)(wr + 8);
            a10[0] = fmaf(h, w0.x, a10[0]);
            a10[1] = fmaf(h, w0.y, a10[1]);
            a10[2] = fmaf(h, w0.z, a10[2]);
            a10[3] = fmaf(h, w0.w, a10[3]);
            a10[4] = fmaf(h, w1.x, a10[4]);
            a10[5] = fmaf(h, w1.y, a10[5]);
            a10[6] = fmaf(h, w1.z, a10[6]);
            a10[7] = fmaf(h, w1.w, a10[7]);
            a10[8] = fmaf(h, w2.x, a10[8]);
            a10[9] = fmaf(h, w2.y, a10[9]);
        }
#pragma unroll
        for (int c = 0; c < 10; c++) {
            a10[c] += __shfl_xor_sync(0xffffffff, a10[c], 1);
            a10[c] += __shfl_xor_sync(0xffffffff, a10[c], 2);
        }
        if (q < 2) {
            const int c0 = q * 5;
            float mu2 = s_mu[b], rs2 = s_rs[b];
            size_t R = ((size_t)f * BATCH + b0 + b) * N_CLASS;
#pragma unroll
            for (int j = 0; j < 5; j++) {
                int c = c0 + j;
                g_Y[R + c] = fmaf(rs2, a10[c] - mu2 * s_s2[c], s_d2[c]);
            }
        }
    }
}

// =====================================================================
// k4: mean over forests
// =====================================================================
__global__ void k4_reduce(float* __restrict__ out) {
    int i = blockIdx.x * 256 + threadIdx.x;
    if (i < BATCH * N_CLASS) {
        float s = 0.f;
        for (int f = 0; f < N_FOREST; f++)
            s += g_Y[(size_t)f * (BATCH * N_CLASS) + i];
        out[i] = s * (1.f / N_FOREST);
    }
}

// =====================================================================
extern "C" void kernel_launch(void* const* d_in, const int* in_sizes, int n_in,
                              void* d_out, int out_size) {
    const float* x     = (const float*)d_in[0];
    const float* w1    = (const float*)d_in[1];
    const float* b1    = (const float*)d_in[2];
    const int*   perm  = (const int*)  d_in[3];
    const float* gn1w  = (const float*)d_in[4];
    const float* gn1b  = (const float*)d_in[5];
    const float* c2w   = (const float*)d_in[6];
    const float* c2b   = (const float*)d_in[7];
    const float* gn2w  = (const float*)d_in[8];
    const float* gn2b  = (const float*)d_in[9];
    const float* c3w   = (const float*)d_in[10];
    const float* c3b   = (const float*)d_in[11];
    const int*   swr   = (const int*)  d_in[12];
    const float* E     = (const float*)d_in[13];
    const float* ln1w  = (const float*)d_in[14];
    const float* ln1b  = (const float*)d_in[15];
    const float* fc1w  = (const float*)d_in[16];
    const float* fc1b  = (const float*)d_in[17];
    const float* ln2w  = (const float*)d_in[18];
    const float* ln2b  = (const float*)d_in[19];
    const float* fc2w  = (const float*)d_in[20];
    const float* fc2b  = (const float*)d_in[21];
    float* out = (float*)d_out;

    cudaFuncSetAttribute(k23_forest_mlp, cudaFuncAttributeMaxDynamicSharedMemorySize, K23_SMEM);

    k0_transpose<<<(N_COL * BATCH) / 256, 256>>>(x);
    k_pre<<<(N_RODT * N_HID + 255) / 256, 256>>>(E, fc1w, ln1w, fc2w, ln2w);
    k_pre2<<<1, 128>>>(fc1w, fc1b, ln1b, fc2w, fc2b, ln2b);
    k1_rodt<<<dim3(N_RODT, BATCH / 256), 256>>>(w1, b1, perm, gn1w, gn1b,
                                                c2w, c2b, gn2w, gn2b, c3w, c3b);
    k23_forest_mlp<<<dim3(BATCH / 128, N_FOREST), 512, K23_SMEM>>>(swr);
    k4_reduce<<<(BATCH * N_CLASS + 255) / 256, 256>>>(out);
}